// round 1
// baseline (speedup 1.0000x reference)
#include <cuda_runtime.h>

// Problem constants
#define BB   2048   // batch
#define HH   2048   // hidden
#define RNK  64     // rank
#define LL   32     // layers

#define KT   64           // K-chunk for GEMM1 (split-K)
#define NK   (HH / KT)    // 32 k-chunks
#define SC   64           // sample chunk
#define HT   64           // h tile for GEMM2
#define TPB  256

// Scratch (device globals — no allocations allowed)
__device__ int    g_offsets[LL + 1];
__device__ int    g_sorted[BB];
__device__ float  g_partial[(size_t)NK * BB * RNK];  // 16 MB split-K partials
__device__ float  g_proj[(size_t)BB * RNK];          // 512 KB

// ---------------------------------------------------------------------------
// Kernel 1: stable counting sort of samples by layer id (deterministic).
// One block, 256 threads. Per-thread histograms over 8-element segments,
// block-wide exclusive scan over the (layer-major, thread-minor) count array.
// ---------------------------------------------------------------------------
__global__ void setup_kernel(const int* __restrict__ ids) {
    __shared__ int A[LL * TPB];   // 8192 ints = 32 KB
    __shared__ int S[TPB];
    int t = threadIdx.x;

    #pragma unroll
    for (int l = 0; l < LL; l++) A[l * TPB + t] = 0;
    // (each thread only touches its own column until the scan)
    int seg = t * (BB / TPB);     // 8 elements per thread
    #pragma unroll
    for (int i = 0; i < BB / TPB; i++) {
        int lid = ids[seg + i];
        A[lid * TPB + t]++;
    }
    __syncthreads();

    // Exclusive scan of A[0..8192): each thread serially scans 32 contiguous
    // elements, then Hillis-Steele scan of the 256 chunk sums.
    int base = t * 32;
    int sum = 0;
    #pragma unroll
    for (int j = 0; j < 32; j++) { int x = A[base + j]; A[base + j] = sum; sum += x; }
    S[t] = sum;
    int mysum = sum;
    __syncthreads();
    for (int d = 1; d < TPB; d <<= 1) {
        int add = (t >= d) ? S[t - d] : 0;
        __syncthreads();
        S[t] += add;
        __syncthreads();
    }
    int excl = S[t] - mysum;
    #pragma unroll
    for (int j = 0; j < 32; j++) A[base + j] += excl;
    __syncthreads();

    if (t < LL) g_offsets[t] = A[t * TPB];
    if (t == 0) g_offsets[LL] = BB;

    // Stable scatter (each thread owns its column counters)
    #pragma unroll
    for (int i = 0; i < BB / TPB; i++) {
        int s = seg + i;
        int lid = ids[s];
        int p = A[lid * TPB + t];
        A[lid * TPB + t] = p + 1;
        g_sorted[p] = s;
    }
}

// ---------------------------------------------------------------------------
// Kernel 2: GEMM1 split-K.  block = (k-chunk, layer).
// partial[kc][b][r] = sum_{k in chunk} v[l][k][r] * z[b][k]
// Thread computes 4 samples x 4 r (16 FMA per k), smem-staged v + transposed z.
// ---------------------------------------------------------------------------
__global__ __launch_bounds__(TPB) void proj_kernel(const float* __restrict__ z,
                                                   const float* __restrict__ v) {
    __shared__ float sv[KT][RNK];        // v tile [k][r], 16 KB
    __shared__ float szT[KT][SC + 4];    // z tile transposed [k][s], padded
    __shared__ int   sgs[SC];

    int t    = threadIdx.x;
    int kc   = blockIdx.x;
    int l    = blockIdx.y;
    int k0   = kc * KT;
    int lane = t & 31, w = t >> 5;
    int rc   = (t & 15) * 4;
    int sc   = (t >> 4) * 4;

    // Load v tile (contiguous: rows [k0, k0+KT) of layer l, R contiguous)
    const float4* vsrc = (const float4*)(v + ((size_t)l * HH + k0) * RNK);
    float4* vdst = (float4*)&sv[0][0];
    #pragma unroll
    for (int i = 0; i < (KT * RNK / 4) / TPB; i++)
        vdst[t + i * TPB] = vsrc[t + i * TPB];

    int off = g_offsets[l];
    int cnt = g_offsets[l + 1] - off;

    for (int c0 = 0; c0 < cnt; c0 += SC) {
        int nc = min(SC, cnt - c0);
        __syncthreads();   // sv ready / previous chunk consumed
        // Stage z chunk transposed: szT[k][s] = z[sorted[s]][k0+k]
        for (int s = w; s < SC; s += 8) {
            if (s < nc) {
                int gs = g_sorted[off + c0 + s];
                if (lane == 0) sgs[s] = gs;
                const float* zrow = z + (size_t)gs * HH + k0;
                szT[lane][s]      = zrow[lane];
                szT[lane + 32][s] = zrow[lane + 32];
            } else {
                szT[lane][s] = 0.0f;
                szT[lane + 32][s] = 0.0f;
            }
        }
        __syncthreads();

        float4 a0 = make_float4(0.f, 0.f, 0.f, 0.f);
        float4 a1 = a0, a2 = a0, a3 = a0;
        #pragma unroll 16
        for (int k = 0; k < KT; k++) {
            float4 vv = *(const float4*)&sv[k][rc];
            float4 zz = *(const float4*)&szT[k][sc];
            a0.x += vv.x * zz.x; a0.y += vv.y * zz.x; a0.z += vv.z * zz.x; a0.w += vv.w * zz.x;
            a1.x += vv.x * zz.y; a1.y += vv.y * zz.y; a1.z += vv.z * zz.y; a1.w += vv.w * zz.y;
            a2.x += vv.x * zz.z; a2.y += vv.y * zz.z; a2.z += vv.z * zz.z; a2.w += vv.w * zz.z;
            a3.x += vv.x * zz.w; a3.y += vv.y * zz.w; a3.z += vv.z * zz.w; a3.w += vv.w * zz.w;
        }

        float* pbase = g_partial + (size_t)kc * BB * RNK;
        if (sc + 0 < nc) *(float4*)&pbase[(size_t)sgs[sc + 0] * RNK + rc] = a0;
        if (sc + 1 < nc) *(float4*)&pbase[(size_t)sgs[sc + 1] * RNK + rc] = a1;
        if (sc + 2 < nc) *(float4*)&pbase[(size_t)sgs[sc + 2] * RNK + rc] = a2;
        if (sc + 3 < nc) *(float4*)&pbase[(size_t)sgs[sc + 3] * RNK + rc] = a3;
    }
}

// ---------------------------------------------------------------------------
// Kernel 3: deterministic split-K reduction: proj = sum_kc partial[kc]
// ---------------------------------------------------------------------------
__global__ void reduce_kernel() {
    int i = blockIdx.x * blockDim.x + threadIdx.x;       // over B*R/4 float4s
    const int n4 = BB * RNK / 4;
    if (i >= n4) return;
    const float4* p = (const float4*)g_partial;
    float4 s = p[i];
    #pragma unroll
    for (int kc = 1; kc < NK; kc++) {
        float4 q = p[(size_t)kc * n4 + i];
        s.x += q.x; s.y += q.y; s.z += q.z; s.w += q.w;
    }
    ((float4*)g_proj)[i] = s;
}

// ---------------------------------------------------------------------------
// Kernel 4: GEMM2 + epilogue.  block = (h-tile, layer).
// out[b][h] = z[b][h] + sum_r u[l][h][r] * proj[b][r]
// u staged transposed [r][h] for vectorized loads; thread = 4 samples x 4 h.
// ---------------------------------------------------------------------------
__global__ __launch_bounds__(TPB) void out_kernel(const float* __restrict__ z,
                                                  const float* __restrict__ u,
                                                  float* __restrict__ out) {
    __shared__ float ut[RNK][HT + 4];    // u transposed [r][h]
    __shared__ float pjT[RNK][SC + 4];   // proj transposed [r][s]
    __shared__ int   sgs[SC];

    int t    = threadIdx.x;
    int lane = t & 31, w = t >> 5;
    int htb  = blockIdx.x;
    int l    = blockIdx.y;
    int h0   = htb * HT;
    int hc   = (t & 15) * 4;
    int sc   = (t >> 4) * 4;

    // Stage u tile transposed: ut[r][h] = u[l][h0+h][r]
    for (int h = w; h < HT; h += 8) {
        const float* urow = u + ((size_t)l * HH + h0 + h) * RNK;
        ut[lane][h]      = urow[lane];
        ut[lane + 32][h] = urow[lane + 32];
    }

    int off = g_offsets[l];
    int cnt = g_offsets[l + 1] - off;

    for (int c0 = 0; c0 < cnt; c0 += SC) {
        int nc = min(SC, cnt - c0);
        __syncthreads();   // ut ready / previous chunk consumed
        for (int s = w; s < SC; s += 8) {
            if (s < nc) {
                int gs = g_sorted[off + c0 + s];
                if (lane == 0) sgs[s] = gs;
                const float* pr = g_proj + (size_t)gs * RNK;
                pjT[lane][s]      = pr[lane];
                pjT[lane + 32][s] = pr[lane + 32];
            } else {
                pjT[lane][s] = 0.0f;
                pjT[lane + 32][s] = 0.0f;
            }
        }
        __syncthreads();

        float4 a0 = make_float4(0.f, 0.f, 0.f, 0.f);
        float4 a1 = a0, a2 = a0, a3 = a0;
        #pragma unroll 16
        for (int r = 0; r < RNK; r++) {
            float4 uu = *(const float4*)&ut[r][hc];
            float4 pp = *(const float4*)&pjT[r][sc];
            a0.x += uu.x * pp.x; a0.y += uu.y * pp.x; a0.z += uu.z * pp.x; a0.w += uu.w * pp.x;
            a1.x += uu.x * pp.y; a1.y += uu.y * pp.y; a1.z += uu.z * pp.y; a1.w += uu.w * pp.y;
            a2.x += uu.x * pp.z; a2.y += uu.y * pp.z; a2.z += uu.z * pp.z; a2.w += uu.w * pp.z;
            a3.x += uu.x * pp.w; a3.y += uu.y * pp.w; a3.z += uu.z * pp.w; a3.w += uu.w * pp.w;
        }

        if (sc + 0 < nc) {
            int gs = sgs[sc + 0];
            float4 zz = *(const float4*)&z[(size_t)gs * HH + h0 + hc];
            float4 o = make_float4(zz.x + a0.x, zz.y + a0.y, zz.z + a0.z, zz.w + a0.w);
            *(float4*)&out[(size_t)gs * HH + h0 + hc] = o;
        }
        if (sc + 1 < nc) {
            int gs = sgs[sc + 1];
            float4 zz = *(const float4*)&z[(size_t)gs * HH + h0 + hc];
            float4 o = make_float4(zz.x + a1.x, zz.y + a1.y, zz.z + a1.z, zz.w + a1.w);
            *(float4*)&out[(size_t)gs * HH + h0 + hc] = o;
        }
        if (sc + 2 < nc) {
            int gs = sgs[sc + 2];
            float4 zz = *(const float4*)&z[(size_t)gs * HH + h0 + hc];
            float4 o = make_float4(zz.x + a2.x, zz.y + a2.y, zz.z + a2.z, zz.w + a2.w);
            *(float4*)&out[(size_t)gs * HH + h0 + hc] = o;
        }
        if (sc + 3 < nc) {
            int gs = sgs[sc + 3];
            float4 zz = *(const float4*)&z[(size_t)gs * HH + h0 + hc];
            float4 o = make_float4(zz.x + a3.x, zz.y + a3.y, zz.z + a3.z, zz.w + a3.w);
            *(float4*)&out[(size_t)gs * HH + h0 + hc] = o;
        }
    }
}

// ---------------------------------------------------------------------------
extern "C" void kernel_launch(void* const* d_in, const int* in_sizes, int n_in,
                              void* d_out, int out_size) {
    const float* z   = (const float*)d_in[0];
    const int*   ids = (const int*)  d_in[1];
    const float* u   = (const float*)d_in[2];
    const float* v   = (const float*)d_in[3];
    float*       out = (float*)d_out;

    setup_kernel<<<1, TPB>>>(ids);
    proj_kernel<<<dim3(NK, LL), TPB>>>(z, v);
    reduce_kernel<<<(BB * RNK / 4 + TPB - 1) / TPB, TPB>>>();
    out_kernel<<<dim3(HH / HT, LL), TPB>>>(z, u, out);
}